// round 1
// baseline (speedup 1.0000x reference)
#include <cuda_runtime.h>

#define TOK   32768
#define DIN   1024
#define RDIM  128
#define NSLOT 4096
#define MAXK  32

// ---------------- scratch (static device arrays; no allocation) ----------------
__device__ float g_hidden[TOK * RDIM];          // 16.8 MB
__device__ float g_scores[134217728];           // TOK * NSLOT = 512 MB
__device__ float g_m[TOK];
__device__ float g_z[TOK];
__device__ int   g_budget[TOK];
__device__ float g_counts[NSLOT];
__device__ float g_aux;

// ---------------- helpers ----------------
__device__ __forceinline__ float warpReduceMaxF(float v) {
#pragma unroll
    for (int o = 16; o > 0; o >>= 1) v = fmaxf(v, __shfl_xor_sync(0xffffffffu, v, o));
    return v;
}
__device__ __forceinline__ float warpReduceSumF(float v) {
#pragma unroll
    for (int o = 16; o > 0; o >>= 1) v += __shfl_xor_sync(0xffffffffu, v, o);
    return v;
}
__device__ __forceinline__ unsigned warpReduceMinU(unsigned v) {
#pragma unroll
    for (int o = 16; o > 0; o >>= 1) {
        unsigned t = __shfl_xor_sync(0xffffffffu, v, o);
        v = (t < v) ? t : v;
    }
    return v;
}

// ---------------- K0: zero counts + aux ----------------
__global__ void k_init() {
    int i = blockIdx.x * blockDim.x + threadIdx.x;
    if (i < NSLOT) g_counts[i] = 0.f;
    if (i == 0)    g_aux = 0.f;
}

// ---------------- K1: hidden = relu(x @ W_h + b_h); budget from sigmoid(x@W_c+b_c) ----------------
// block: 128 tokens x 128 outputs (all of R), 256 threads, 8x8 per thread, K-tiles of 32
__global__ __launch_bounds__(256) void k_hidden(
    const float* __restrict__ x,  const float* __restrict__ Wc, const float* __restrict__ bc,
    const float* __restrict__ Wh, const float* __restrict__ bh, float* __restrict__ out_b)
{
    __shared__ float Xs[32][132];   // transposed x tile [k][token], padded
    __shared__ float Wsm[32][128];  // W_h tile [k][n]
    __shared__ float Wcs[32];

    const int tid = threadIdx.x;
    const int tx = tid & 15, ty = tid >> 4;
    const int t0 = blockIdx.x * 128;

    float acc[8][8];
#pragma unroll
    for (int j = 0; j < 8; j++) {
        int c = (j < 4) ? tx * 4 + j : 64 + tx * 4 + (j - 4);
        float b = bh[c];
#pragma unroll
        for (int i = 0; i < 8; i++) acc[i][j] = b;
    }
    float cacc = 0.f;

    for (int kt = 0; kt < 32; kt++) {
#pragma unroll
        for (int i = 0; i < 4; i++) {
            int id = tid + i * 256;           // over 128 tokens x 8 float4
            int token = id >> 3, kg = id & 7;
            float4 f = *(const float4*)(x + (size_t)(t0 + token) * DIN + kt * 32 + kg * 4);
            Xs[kg * 4 + 0][token] = f.x; Xs[kg * 4 + 1][token] = f.y;
            Xs[kg * 4 + 2][token] = f.z; Xs[kg * 4 + 3][token] = f.w;
        }
#pragma unroll
        for (int i = 0; i < 4; i++) {
            int id = tid + i * 256;           // over 32 rows x 32 float4
            int rowk = id >> 5, ng = id & 31;
            *(float4*)&Wsm[rowk][ng * 4] =
                *(const float4*)(Wh + (size_t)(kt * 32 + rowk) * RDIM + ng * 4);
        }
        if (tid < 32) Wcs[tid] = Wc[kt * 32 + tid];
        __syncthreads();

#pragma unroll
        for (int k = 0; k < 32; k++) {
            float4 a0 = *(float4*)&Xs[k][ty * 4];
            float4 a1 = *(float4*)&Xs[k][64 + ty * 4];
            float4 b0 = *(float4*)&Wsm[k][tx * 4];
            float4 b1 = *(float4*)&Wsm[k][64 + tx * 4];
            float xf[8] = {a0.x, a0.y, a0.z, a0.w, a1.x, a1.y, a1.z, a1.w};
            float wf[8] = {b0.x, b0.y, b0.z, b0.w, b1.x, b1.y, b1.z, b1.w};
#pragma unroll
            for (int i = 0; i < 8; i++)
#pragma unroll
                for (int j = 0; j < 8; j++)
                    acc[i][j] += xf[i] * wf[j];
        }
        if (tid < 128) {
            float s = 0.f;
#pragma unroll
            for (int k = 0; k < 32; k++) s += Xs[k][tid] * Wcs[k];
            cacc += s;
        }
        __syncthreads();
    }

#pragma unroll
    for (int i = 0; i < 8; i++) {
        int r = (i < 4) ? ty * 4 + i : 64 + ty * 4 + (i - 4);
        float4 o0 = make_float4(fmaxf(acc[i][0], 0.f), fmaxf(acc[i][1], 0.f),
                                fmaxf(acc[i][2], 0.f), fmaxf(acc[i][3], 0.f));
        float4 o1 = make_float4(fmaxf(acc[i][4], 0.f), fmaxf(acc[i][5], 0.f),
                                fmaxf(acc[i][6], 0.f), fmaxf(acc[i][7], 0.f));
        *(float4*)(g_hidden + (size_t)(t0 + r) * RDIM + tx * 4) = o0;
        *(float4*)(g_hidden + (size_t)(t0 + r) * RDIM + 64 + tx * 4) = o1;
    }
    if (tid < 128) {
        float zc = cacc + bc[0];
        float c = 1.f / (1.f + expf(-zc));
        float bf = 4.f + 28.f * c * c;
        int b = (int)floorf(bf);
        g_budget[t0 + tid] = b;
        out_b[t0 + tid] = (float)b;
    }
}

// ---------------- K2: scores = hidden @ W_s + b_s (materialize 512 MB) ----------------
// block: 128 tokens, loops over 32 N-tiles of 128; K=128 fully resident
__global__ __launch_bounds__(256) void k_scores(const float* __restrict__ Wsg,
                                                const float* __restrict__ bs)
{
    extern __shared__ float sm[];
    float* Hs = sm;                 // [128][132] transposed hidden
    float* Wt = sm + 128 * 132;     // [128][132] W_s tile

    const int tid = threadIdx.x;
    const int tx = tid & 15, ty = tid >> 4;
    const int t0 = blockIdx.x * 128;

#pragma unroll
    for (int i = 0; i < 16; i++) {
        int id = tid + i * 256;       // 128 tokens x 32 float4
        int token = id >> 5, kg = id & 31;
        float4 f = *(const float4*)(g_hidden + (size_t)(t0 + token) * RDIM + kg * 4);
        Hs[(kg * 4 + 0) * 132 + token] = f.x;
        Hs[(kg * 4 + 1) * 132 + token] = f.y;
        Hs[(kg * 4 + 2) * 132 + token] = f.z;
        Hs[(kg * 4 + 3) * 132 + token] = f.w;
    }

    for (int nt = 0; nt < 32; nt++) {
        __syncthreads();
#pragma unroll
        for (int i = 0; i < 16; i++) {
            int id = tid + i * 256;   // 128 rows x 32 float4
            int rowk = id >> 5, ng = id & 31;
            *(float4*)&Wt[rowk * 132 + ng * 4] =
                *(const float4*)(Wsg + (size_t)rowk * NSLOT + nt * 128 + ng * 4);
        }
        __syncthreads();

        float acc[8][8];
#pragma unroll
        for (int j = 0; j < 8; j++) {
            int c = (j < 4) ? tx * 4 + j : 64 + tx * 4 + (j - 4);
            float b = bs[nt * 128 + c];
#pragma unroll
            for (int i = 0; i < 8; i++) acc[i][j] = b;
        }
#pragma unroll 8
        for (int k = 0; k < 128; k++) {
            float4 a0 = *(float4*)&Hs[k * 132 + ty * 4];
            float4 a1 = *(float4*)&Hs[k * 132 + 64 + ty * 4];
            float4 b0 = *(float4*)&Wt[k * 132 + tx * 4];
            float4 b1 = *(float4*)&Wt[k * 132 + 64 + tx * 4];
            float xf[8] = {a0.x, a0.y, a0.z, a0.w, a1.x, a1.y, a1.z, a1.w};
            float wf[8] = {b0.x, b0.y, b0.z, b0.w, b1.x, b1.y, b1.z, b1.w};
#pragma unroll
            for (int i = 0; i < 8; i++)
#pragma unroll
                for (int j = 0; j < 8; j++)
                    acc[i][j] += xf[i] * wf[j];
        }
#pragma unroll
        for (int i = 0; i < 8; i++) {
            int r = (i < 4) ? ty * 4 + i : 64 + ty * 4 + (i - 4);
            float4 o0 = make_float4(acc[i][0], acc[i][1], acc[i][2], acc[i][3]);
            float4 o1 = make_float4(acc[i][4], acc[i][5], acc[i][6], acc[i][7]);
            *(float4*)(g_scores + (size_t)(t0 + r) * NSLOT + nt * 128 + tx * 4) = o0;
            *(float4*)(g_scores + (size_t)(t0 + r) * NSLOT + nt * 128 + 64 + tx * 4) = o1;
        }
    }
}

// ---------------- K3: per-token top-32 (exact, jax tie-break), weights, m/Z, counts ----------------
__global__ __launch_bounds__(256) void k_topk(float* __restrict__ out_idx,
                                              float* __restrict__ out_w)
{
    __shared__ unsigned hist[256];
    __shared__ float    sred[8];
    __shared__ unsigned ured[8];
    __shared__ unsigned selKey[MAXK];
    __shared__ unsigned selIdx[MAXK];
    __shared__ unsigned s_cnt, s_d, s_kneed, s_eq;
    __shared__ float    s_bcast;

    const int t = blockIdx.x;
    const int tid = threadIdx.x, lane = tid & 31, wid = tid >> 5;
    const float* row = g_scores + (size_t)t * NSLOT;

    float v[16]; unsigned key[16];
#pragma unroll
    for (int i = 0; i < 4; i++) {
        float4 f = *(const float4*)(row + (size_t)(tid + i * 256) * 4);
        v[i * 4 + 0] = f.x; v[i * 4 + 1] = f.y; v[i * 4 + 2] = f.z; v[i * 4 + 3] = f.w;
    }
#pragma unroll
    for (int i = 0; i < 16; i++) {
        unsigned b = __float_as_uint(v[i]);
        key[i] = b ^ ((unsigned)((int)b >> 31) | 0x80000000u);  // sortable uint
    }

    // row max
    float m = v[0];
#pragma unroll
    for (int i = 1; i < 16; i++) m = fmaxf(m, v[i]);
    m = warpReduceMaxF(m);
    if (lane == 0) sred[wid] = m;
    __syncthreads();
    if (tid == 0) { float mm = sred[0]; for (int i = 1; i < 8; i++) mm = fmaxf(mm, sred[i]); s_bcast = mm; }
    __syncthreads();
    m = s_bcast;

    // Z = sum exp(v - m)
    float z = 0.f;
#pragma unroll
    for (int i = 0; i < 16; i++) z += expf(v[i] - m);
    z = warpReduceSumF(z);
    __syncthreads();
    if (lane == 0) sred[wid] = z;
    __syncthreads();
    if (tid == 0) { float zz = 0.f; for (int i = 0; i < 8; i++) zz += sred[i]; g_m[t] = m; g_z[t] = zz; }

    // radix-select: exact key of the 32nd largest
    unsigned prefix = 0, pmask = 0, kneed = MAXK;
    for (int shift = 24; shift >= 0; shift -= 8) {
        hist[tid] = 0;
        __syncthreads();
#pragma unroll
        for (int i = 0; i < 16; i++)
            if ((key[i] & pmask) == prefix) atomicAdd(&hist[(key[i] >> shift) & 255], 1u);
        __syncthreads();
        if (wid == 0) {
            unsigned h[8]; unsigned csum = 0;
#pragma unroll
            for (int j = 0; j < 8; j++) { h[j] = hist[lane * 8 + j]; csum += h[j]; }
            unsigned s = csum;
#pragma unroll
            for (int o = 1; o < 32; o <<= 1) {
                unsigned tt = __shfl_down_sync(0xffffffffu, s, o);
                if (lane + o < 32) s += tt;
            }
            unsigned run = s - csum;   // count strictly above this lane's chunk
#pragma unroll
            for (int j = 7; j >= 0; j--) {
                unsigned nxt = run + h[j];
                if (nxt >= kneed && run < kneed) { s_d = (unsigned)(lane * 8 + j); s_kneed = kneed - run; }
                run = nxt;
            }
        }
        __syncthreads();
        unsigned d = s_d;
        kneed = s_kneed;
        prefix |= d << shift;
        pmask |= 255u << shift;
    }
    const unsigned thresh = prefix;

    // gather strictly-greater
    if (tid == 0) s_cnt = 0;
    __syncthreads();
#pragma unroll
    for (int i = 0; i < 16; i++) {
        if (key[i] > thresh) {
            unsigned p = atomicAdd(&s_cnt, 1u);
            selKey[p] = key[i];
            selIdx[p] = (unsigned)((tid + (i >> 2) * 256) * 4 + (i & 3));
        }
    }
    __syncthreads();
    const unsigned nG = s_cnt;

    // equals at threshold: take kneed smallest indices (jax tie-break)
    int lastIdx = -1;
    for (unsigned e = 0; e < kneed; e++) {
        unsigned best = 0xFFFFFFFFu;
#pragma unroll
        for (int i = 0; i < 16; i++) {
            unsigned idx = (unsigned)((tid + (i >> 2) * 256) * 4 + (i & 3));
            if (key[i] == thresh && (int)idx > lastIdx) best = (idx < best) ? idx : best;
        }
        best = warpReduceMinU(best);
        if (lane == 0) ured[wid] = best;
        __syncthreads();
        if (tid == 0) {
            unsigned bb = ured[0];
            for (int i = 1; i < 8; i++) bb = (ured[i] < bb) ? ured[i] : bb;
            s_eq = bb;
            selKey[nG + e] = thresh;
            selIdx[nG + e] = bb;
        }
        __syncthreads();
        lastIdx = (int)s_eq;
    }
    __syncthreads();

    // warp 0: bitonic sort 32 (value desc, index asc), weights, outputs
    if (wid == 0) {
        unsigned long long kk =
            ((unsigned long long)selKey[lane] << 32) |
            (unsigned long long)(0xFFFFFFFFu - selIdx[lane]);
#pragma unroll
        for (int k2 = 2; k2 <= 32; k2 <<= 1) {
#pragma unroll
            for (int j = k2 >> 1; j > 0; j >>= 1) {
                unsigned long long o = __shfl_xor_sync(0xffffffffu, kk, j);
                bool up = ((lane & k2) == 0);
                bool low = ((lane & j) == 0);
                unsigned long long mx = (kk > o) ? kk : o;
                unsigned long long mn = (kk > o) ? o : kk;
                kk = (up == low) ? mx : mn;   // descending
            }
        }
        unsigned keyv = (unsigned)(kk >> 32);
        unsigned idxv = 0xFFFFFFFFu - (unsigned)(kk & 0xFFFFFFFFull);
        unsigned fb = (keyv & 0x80000000u) ? (keyv ^ 0x80000000u) : ~keyv;
        float val = __uint_as_float(fb);

        int b = g_budget[t];
        float v0 = __shfl_sync(0xffffffffu, val, 0);
        bool msk = lane < b;
        float ev = msk ? expf(val - v0) : 0.f;
        float zz = warpReduceSumF(ev);
        float w = msk ? ev / zz : 0.f;

        out_idx[t * MAXK + lane] = (float)idxv;
        out_w[t * MAXK + lane] = w;
        if (msk) atomicAdd(&g_counts[idxv], 1.0f);
    }
}

// ---------------- K4: aux partial = (N/T^2) * sum_n p_tn * counts[n] ----------------
__global__ __launch_bounds__(256) void k_aux()
{
    __shared__ float sred[8];
    const int t = blockIdx.x;
    const int tid = threadIdx.x, lane = tid & 31, wid = tid >> 5;
    const float* row = g_scores + (size_t)t * NSLOT;
    const float m = g_m[t];
    const float zi = 1.f / g_z[t];
    float s = 0.f;
#pragma unroll
    for (int i = 0; i < 16; i++) {
        int n = tid + i * 256;
        s += expf(row[n] - m) * g_counts[n];
    }
    s = warpReduceSumF(s);
    if (lane == 0) sred[wid] = s;
    __syncthreads();
    if (tid == 0) {
        float ss = 0.f;
        for (int i = 0; i < 8; i++) ss += sred[i];
        float contrib = ss * zi * ((float)NSLOT / ((float)TOK * (float)TOK));
        atomicAdd(&g_aux, contrib);
    }
}

// ---------------- K5: publish aux ----------------
__global__ void k_finish(float* __restrict__ out_aux)
{
    if (threadIdx.x == 0) out_aux[0] = g_aux;
}

// ---------------- launch ----------------
extern "C" void kernel_launch(void* const* d_in, const int* in_sizes, int n_in,
                              void* d_out, int out_size)
{
    const float* x  = (const float*)d_in[0];
    const float* Wc = (const float*)d_in[1];
    const float* bc = (const float*)d_in[2];
    const float* Wh = (const float*)d_in[3];
    const float* bh = (const float*)d_in[4];
    const float* Ws = (const float*)d_in[5];
    const float* bs = (const float*)d_in[6];

    float* out     = (float*)d_out;
    float* out_idx = out;                            // (B,S,32) top_i as float
    float* out_w   = out + TOK * MAXK;               // (B,S,32) weights
    float* out_b   = out + 2 * TOK * MAXK;           // (B,S,1) budget as float
    float* out_aux = out + 2 * TOK * MAXK + TOK;     // scalar aux_loss

    const int smem2 = 2 * 128 * 132 * (int)sizeof(float);  // 135168 B
    cudaFuncSetAttribute(k_scores, cudaFuncAttributeMaxDynamicSharedMemorySize, smem2);

    k_init<<<(NSLOT + 255) / 256, 256>>>();
    k_hidden<<<TOK / 128, 256>>>(x, Wc, bc, Wh, bh, out_b);
    k_scores<<<TOK / 128, 256, smem2>>>(Ws, bs);
    k_topk<<<TOK, 256>>>(out_idx, out_w);
    k_aux<<<TOK, 256>>>();
    k_finish<<<1, 32>>>(out_aux);
}